// round 5
// baseline (speedup 1.0000x reference)
#include <cuda_runtime.h>
#include <cstdint>

// Problem constants (fixed by the reference)
static constexpr int TOKEN_NUM  = 300;
static constexpr int HALF       = 76800;                    // 256*300
static constexpr int TOTAL      = 614400;                   // 4*2*HALF

// u64 packing: low 32 = count, high 32 = Q21 fixed-point wt sum.
// Per-bin counts ~Poisson(27) << 2^(32-21)=2048 -> no carry into count field.
static constexpr float WT_SCALE     = 2097152.0f;           // 2^21
static constexpr float WT_INV_SCALE = 1.0f / 2097152.0f;

__device__ unsigned long long g_scratch[TOTAL];

static constexpr int THREADS          = 512;
static constexpr int TILE             = 1024;   // events/tile = 16KB
static constexpr int STAGES           = 2;
static constexpr int TILES_PER_BLOCK  = 8;      // 8192 events per block

__device__ __forceinline__ unsigned smem_u32(const void* p) {
    return (unsigned)__cvta_generic_to_shared(p);
}

__device__ __forceinline__ void mbar_wait_parity(unsigned mb, unsigned parity) {
    asm volatile(
        "{\n\t"
        ".reg .pred P1;\n\t"
        "WAIT_LOOP_%=:\n\t"
        "mbarrier.try_wait.parity.acquire.cta.shared::cta.b64 P1, [%0], %1, 0x989680;\n\t"
        "@P1 bra.uni WAIT_DONE_%=;\n\t"
        "bra.uni WAIT_LOOP_%=;\n\t"
        "WAIT_DONE_%=:\n\t"
        "}"
        :: "r"(mb), "r"(parity) : "memory");
}

__global__ void __launch_bounds__(THREADS, 1)
hist_kernel(const float4* __restrict__ x4, int n, int tiles_total) {
    __shared__ __align__(16) float4 buf[STAGES][TILE];
    __shared__ unsigned long long mbar[STAGES];

    const int tid   = threadIdx.x;
    const int tile0 = blockIdx.x * TILES_PER_BLOCK;
    const int ntiles = min(TILES_PER_BLOCK, tiles_total - tile0);
    if (ntiles <= 0) return;

    if (tid == 0) {
        #pragma unroll
        for (int s = 0; s < STAGES; s++) {
            unsigned a = smem_u32(&mbar[s]);
            asm volatile("mbarrier.init.shared.b64 [%0], 1;" :: "r"(a) : "memory");
        }
    }
    __syncthreads();

    const float DIVW     = (float)(319.0 / 20.0 + 0.0001);
    const float DIVH     = (float)(239.0 / 15.0 + 0.0001);
    const float INV_DIVW = (float)(1.0 / (319.0 / 20.0 + 0.0001));
    const float INV_DIVH = (float)(1.0 / (239.0 / 15.0 + 0.0001));

    const float t0 = __ldg(&x4[0].x);
    const float tl = __ldg(&x4[n - 1].x);
    const float inv_b = 1.0f / (tl - t0 + 0.0001f);   // for wt
    const float inv_d = 4.0f / (tl - t0 + 1.0f);      // TIME_DIV / (range + 1)

    // Prologue: fill both stages
    if (tid == 0) {
        #pragma unroll
        for (int s = 0; s < STAGES; s++) {
            if (s < ntiles) {
                int start = (tile0 + s) * TILE;
                unsigned bytes = (unsigned)min(TILE, n - start) * 16u;
                unsigned mb  = smem_u32(&mbar[s]);
                unsigned dst = smem_u32(&buf[s][0]);
                asm volatile("mbarrier.arrive.expect_tx.shared.b64 _, [%0], %1;"
                             :: "r"(mb), "r"(bytes) : "memory");
                asm volatile("cp.async.bulk.shared::cta.global.mbarrier::complete_tx::bytes "
                             "[%0], [%1], %2, [%3];"
                             :: "r"(dst), "l"(x4 + start), "r"(bytes), "r"(mb) : "memory");
            }
        }
    }

    int ph[STAGES];
    #pragma unroll
    for (int s = 0; s < STAGES; s++) ph[s] = 0;

    for (int k = 0; k < ntiles; k++) {
        const int s = k % STAGES;
        mbar_wait_parity(smem_u32(&mbar[s]), (unsigned)ph[s]);
        ph[s] ^= 1;

        const int start = (tile0 + k) * TILE;
        const int cnt   = min(TILE, n - start);

        #pragma unroll
        for (int j = tid; j < cnt; j += THREADS) {
            const float4 e = buf[s][j];
            const float t  = e.x;
            const float xs = e.y;
            const float ys = e.z;
            const float p  = e.w;

            const unsigned w  = (p != 2.0f) ? 1u : 0u;
            const float    wt = (t - t0) * inv_b;

            const float px   = floorf(xs * INV_DIVW);
            const float py   = floorf(ys * INV_DIVH);
            const float posf = fmaf(py, 20.0f, px);
            const float tokx = floorf(fmaf(-DIVW, px, xs));
            const float toky = floorf(fmaf(-DIVH, py, ys));
            const float tokf = fmaf(toky, 16.0f, tokx);
            const float dtf  = floorf((t - t0) * inv_d);

            // clip to [0, bins] (upper bound INCLUSIVE, matching jnp.clip)
            int d  = min(max((int)dtf,  0), 4);
            int pi = min(max((int)p,    0), 2);
            int tk = min(max((int)tokf, 0), 256);
            int ps = min(max((int)posf, 0), 300);

            int l = d * (2 * HALF) + pi * HALF + tk * TOKEN_NUM + ps;
            if (l < TOTAL) {   // segment_sum drops out-of-range segments
                unsigned wtq = (unsigned)(wt * WT_SCALE + 0.5f);
                atomicAdd(&g_scratch[l],
                          (unsigned long long)w | ((unsigned long long)wtq << 32));
            }
        }
        __syncthreads();   // all threads done reading stage s

        const int nk = k + STAGES;
        if (tid == 0 && nk < ntiles) {
            int start2 = (tile0 + nk) * TILE;
            unsigned bytes2 = (unsigned)min(TILE, n - start2) * 16u;
            unsigned mb  = smem_u32(&mbar[s]);
            unsigned dst = smem_u32(&buf[s][0]);
            asm volatile("mbarrier.arrive.expect_tx.shared.b64 _, [%0], %1;"
                         :: "r"(mb), "r"(bytes2) : "memory");
            asm volatile("cp.async.bulk.shared::cta.global.mbarrier::complete_tx::bytes "
                         "[%0], [%1], %2, [%3];"
                         :: "r"(dst), "l"(x4 + start2), "r"(bytes2), "r"(mb) : "memory");
        }
    }
}

__global__ void zero_scratch_kernel() {
    int i = blockIdx.x * blockDim.x + threadIdx.x;
    ulonglong2* p = (ulonglong2*)g_scratch;     // TOTAL/2 = 307200 vectors
    #pragma unroll
    for (int k = 0; k < 4; k++) {
        int j = i + k * 76800;
        p[j] = make_ulonglong2(0ull, 0ull);     // 4*76800 = 307200 exactly
    }
}

// 4 bins/thread: two ulonglong2 loads, two aligned float4 stores.
// HALF % 4 == 0, so all 4 bins share the same hi block and base % 4 == 0.
__global__ void finalize_kernel(float* __restrict__ out) {
    int j = blockIdx.x * blockDim.x + threadIdx.x;
    if (j >= TOTAL / 4) return;
    int l0 = j * 4;

    ulonglong2 v01 = ((const ulonglong2*)g_scratch)[j * 2];
    ulonglong2 v23 = ((const ulonglong2*)g_scratch)[j * 2 + 1];

    int hi   = l0 / HALF;          // (dtime*2 + p) in [0,8)
    int lo   = l0 - hi * HALF;
    int base = hi * (2 * HALF) + lo;

    float4 cnt = make_float4((float)(unsigned)(v01.x & 0xFFFFFFFFull),
                             (float)(unsigned)(v01.y & 0xFFFFFFFFull),
                             (float)(unsigned)(v23.x & 0xFFFFFFFFull),
                             (float)(unsigned)(v23.y & 0xFFFFFFFFull));
    float4 wts = make_float4((float)(unsigned)(v01.x >> 32) * WT_INV_SCALE,
                             (float)(unsigned)(v01.y >> 32) * WT_INV_SCALE,
                             (float)(unsigned)(v23.x >> 32) * WT_INV_SCALE,
                             (float)(unsigned)(v23.y >> 32) * WT_INV_SCALE);

    ((float4*)(out + base))[0]        = cnt;
    ((float4*)(out + base + HALF))[0] = wts;
}

extern "C" void kernel_launch(void* const* d_in, const int* in_sizes, int n_in,
                              void* d_out, int out_size) {
    const float4* x4 = (const float4*)d_in[0];
    float* out = (float*)d_out;
    const int n = in_sizes[0] / 4;   // events

    const int tiles_total = (n + TILE - 1) / TILE;
    const int grid = (tiles_total + TILES_PER_BLOCK - 1) / TILES_PER_BLOCK;

    zero_scratch_kernel<<<300, 256>>>();                         // 76800 threads * 64B
    hist_kernel<<<grid, THREADS>>>(x4, n, tiles_total);
    finalize_kernel<<<(TOTAL / 4 + 255) / 256, 256>>>(out);
}

// round 6
// speedup vs baseline: 1.0187x; 1.0187x over previous
#include <cuda_runtime.h>

// Problem constants (fixed by the reference)
static constexpr int TOKEN_NUM  = 300;
static constexpr int PATCH_SIZE = 256;
static constexpr int HALF       = PATCH_SIZE * TOKEN_NUM;   // 76800
static constexpr int TOTAL      = 4 * 2 * HALF;             // 614400

// u64 packing: low 32 = count, high 32 = Q21 fixed-point wt sum.
// Per-bin counts ~Poisson(27) << 2^(32-21)=2048 -> no carry into count field.
static constexpr float WT_SCALE     = 2097152.0f;           // 2^21
static constexpr float WT_INV_SCALE = 1.0f / 2097152.0f;

// Zero at module load; finalize_kernel re-zeros after reading, so every
// execution (including every graph replay) starts from zeros.
__device__ unsigned long long g_scratch[TOTAL];

__global__ void hist_kernel(const float4* __restrict__ x4, int n) {
    const float DIVW = (float)(319.0 / 20.0 + 0.0001);   // W/PW + B
    const float DIVH = (float)(239.0 / 15.0 + 0.0001);   // H/PH + B

    const float t0 = __ldg(&x4[0].x);
    const float tl = __ldg(&x4[n - 1].x);
    const float inv_b = 1.0f / (tl - t0 + 0.0001f);      // for wt
    const float inv_d = 4.0f / (tl - t0 + 1.0f);         // TIME_DIV / (range + 1)

    int i = blockIdx.x * blockDim.x + threadIdx.x;
    if (i >= n) return;

    const float4 e = x4[i];   // (t, xs, ys, p)
    const float t  = e.x;
    const float xs = e.y;
    const float ys = e.z;
    const float p  = e.w;

    const unsigned int w  = (p != 2.0f) ? 1u : 0u;
    const float        wt = (t - t0) * inv_b;

    const float posf = floorf(xs / DIVW) + floorf(ys / DIVH) * 20.0f;
    const float tokf = floorf(fmodf(xs, DIVW)) + floorf(fmodf(ys, DIVH)) * 16.0f;
    const float dtf  = floorf((t - t0) * inv_d);

    // clip to [0, bins] (upper bound INCLUSIVE, matching jnp.clip(x, 0, bins))
    int d  = min(max((int)dtf,  0), 4);
    int pi = min(max((int)p,    0), 2);
    int tk = min(max((int)tokf, 0), 256);
    int ps = min(max((int)posf, 0), 300);

    int l = d * (2 * HALF) + pi * HALF + tk * TOKEN_NUM + ps;
    if (l >= TOTAL) return;   // segment_sum drops out-of-range segments

    unsigned int wtq = (unsigned int)(wt * WT_SCALE + 0.5f);
    atomicAdd(&g_scratch[l],
              (unsigned long long)w | ((unsigned long long)wtq << 32));
}

// Self-cleaning finalize: 4 bins/thread. Two ulonglong2 loads, two aligned
// float4 output stores, two ulonglong2 zero-stores (scratch clean for the
// next replay). HALF % 4 == 0 so all 4 bins share one hi block; base % 4 == 0.
__global__ void finalize_kernel(float* __restrict__ out) {
    int j = blockIdx.x * blockDim.x + threadIdx.x;
    if (j >= TOTAL / 4) return;
    int l0 = j * 4;

    ulonglong2* sp = (ulonglong2*)g_scratch;
    ulonglong2 v01 = sp[j * 2];
    ulonglong2 v23 = sp[j * 2 + 1];
    sp[j * 2]     = make_ulonglong2(0ull, 0ull);
    sp[j * 2 + 1] = make_ulonglong2(0ull, 0ull);

    int hi   = l0 / HALF;          // (dtime*2 + p) in [0,8)
    int lo   = l0 - hi * HALF;
    int base = hi * (2 * HALF) + lo;

    float4 cnt = make_float4((float)(unsigned)(v01.x & 0xFFFFFFFFull),
                             (float)(unsigned)(v01.y & 0xFFFFFFFFull),
                             (float)(unsigned)(v23.x & 0xFFFFFFFFull),
                             (float)(unsigned)(v23.y & 0xFFFFFFFFull));
    float4 wts = make_float4((float)(unsigned)(v01.x >> 32) * WT_INV_SCALE,
                             (float)(unsigned)(v01.y >> 32) * WT_INV_SCALE,
                             (float)(unsigned)(v23.x >> 32) * WT_INV_SCALE,
                             (float)(unsigned)(v23.y >> 32) * WT_INV_SCALE);

    ((float4*)(out + base))[0]        = cnt;
    ((float4*)(out + base + HALF))[0] = wts;
}

extern "C" void kernel_launch(void* const* d_in, const int* in_sizes, int n_in,
                              void* d_out, int out_size) {
    const float4* x4 = (const float4*)d_in[0];
    float* out = (float*)d_out;
    const int n = in_sizes[0] / 4;   // events

    hist_kernel<<<(n + 255) / 256, 256>>>(x4, n);
    finalize_kernel<<<(TOTAL / 4 + 255) / 256, 256>>>(out);
}